// round 15
// baseline (speedup 1.0000x reference)
#include <cuda_runtime.h>
#include <cuda_bf16.h>
#include <cstdint>

// Problem dims (fixed by the dataset)
#define D_IN   2048
#define D_OUT  8192
#define M_TOT  16384   // B*S

// GEMM tiling (baseline-ISA int8 mma.sync path; tcgen05 is unavailable:
// the bench toolchain lowers via plain compute_103 PTX, which rejects all
// sm_103a-gated instructions)
#define BM 128
#define BN 128
#define BK 64
#define NKT (D_IN / BK)            // 32
#define STAGES 4
#define STAGE_BYTES (BM * 64 + BN * 64)      // 16384 (A tile 8KB + B tile 8KB, int8)
#define SMEM_BYTES (STAGES * STAGE_BYTES)    // 65536

// -------------------- device scratch (static: no cudaMalloc) --------------------
__device__ double g_partial[4096];
__device__ float  g_ws;
__device__ int8_t g_wt[(size_t)D_OUT * D_IN];  // ternary weights {-1,0,1} as s8
__device__ int8_t g_xa[(size_t)M_TOT * D_IN];  // quantized activations as s8
__device__ float  g_rowscale[M_TOT];           // cmax/127 per row

// -------------------- PTX helpers (baseline sm_80 features only) ----------------
__device__ __forceinline__ uint32_t smem_u32(const void* p) {
    uint32_t a;
    asm("{ .reg .u64 t; cvta.to.shared.u64 t, %1; cvt.u32.u64 %0, t; }" : "=r"(a) : "l"(p));
    return a;
}

#define CP_ASYNC16(dst, src) \
    asm volatile("cp.async.cg.shared.global [%0], [%1], 16;" :: "r"(dst), "l"(src) : "memory")
#define CP_COMMIT() asm volatile("cp.async.commit_group;" ::: "memory")
#define CP_WAIT(n)  asm volatile("cp.async.wait_group %0;" :: "n"(n) : "memory")

#define LDSM_X4(r, addr) \
    asm volatile("ldmatrix.sync.aligned.m8n8.x4.shared.b16 {%0,%1,%2,%3}, [%4];" \
        : "=r"((r)[0]), "=r"((r)[1]), "=r"((r)[2]), "=r"((r)[3]) : "r"(addr))

#define MMA_S8(d, a, b0, b1) \
    asm volatile("mma.sync.aligned.m16n8k32.row.col.s32.s8.s8.s32 " \
        "{%0,%1,%2,%3}, {%4,%5,%6,%7}, {%8,%9}, {%0,%1,%2,%3};" \
        : "+r"((d)[0]), "+r"((d)[1]), "+r"((d)[2]), "+r"((d)[3]) \
        : "r"((a)[0]), "r"((a)[1]), "r"((a)[2]), "r"((a)[3]), "r"(b0), "r"(b1))

// XOR-permuted int8 tile layout: row r (64 bytes/row), 16B-column c (0..3).
// Bank-group g = (r%2)*4 + (c ^ ((r>>1)&3)) is distinct across any 8 rows at
// fixed c -> conflict-free ldmatrix, and conflict-free 16B cp.async stores.
__device__ __forceinline__ uint32_t swz(int r, int c) {
    return (uint32_t)(r * 64 + ((c ^ ((r >> 1) & 3)) << 4));
}

// -------------------- prep kernels --------------------
__global__ void k_wsum1(const float* __restrict__ w) {
    __shared__ double sh[256];
    int t = threadIdx.x;
    size_t base = (size_t)blockIdx.x * 4096 + t;
    double s = 0.0;
#pragma unroll
    for (int i = 0; i < 16; i++) s += (double)fabsf(w[base + i * 256]);
    sh[t] = s; __syncthreads();
    for (int o = 128; o > 0; o >>= 1) { if (t < o) sh[t] += sh[t + o]; __syncthreads(); }
    if (t == 0) g_partial[blockIdx.x] = sh[0];
}

__global__ void k_wsum2() {
    __shared__ double sh[256];
    int t = threadIdx.x;
    double s = 0.0;
#pragma unroll
    for (int i = 0; i < 16; i++) s += g_partial[t + i * 256];
    sh[t] = s; __syncthreads();
    for (int o = 128; o > 0; o >>= 1) { if (t < o) sh[t] += sh[t + o]; __syncthreads(); }
    if (t == 0) {
        double m = sh[0] / 16777216.0;
        if (m < 1e-8) m = 1e-8;
        g_ws = (float)m;
    }
}

__global__ void k_tern(const float* __restrict__ w) {
    float inv = 1.0f / g_ws;
    int i = blockIdx.x * 256 + threadIdx.x;       // one float4 -> 4 s8
    float4 v = reinterpret_cast<const float4*>(w)[i];
    int a = (int)fminf(fmaxf(rintf(v.x * inv), -1.f), 1.f);
    int b = (int)fminf(fmaxf(rintf(v.y * inv), -1.f), 1.f);
    int c = (int)fminf(fmaxf(rintf(v.z * inv), -1.f), 1.f);
    int d = (int)fminf(fmaxf(rintf(v.w * inv), -1.f), 1.f);
    uint32_t p = (uint32_t)(a & 0xFF) | ((uint32_t)(b & 0xFF) << 8)
               | ((uint32_t)(c & 0xFF) << 16) | ((uint32_t)(d & 0xFF) << 24);
    reinterpret_cast<uint32_t*>(g_wt)[i] = p;
}

// RMSNorm + absmax + int8 quant, one block per row
__global__ void k_actq(const float* __restrict__ x, const float* __restrict__ gamma) {
    __shared__ float sh[256];
    int m = blockIdx.x;
    int t = threadIdx.x;
    const float4* xr = reinterpret_cast<const float4*>(x + (size_t)m * D_IN);
    const float4* g4 = reinterpret_cast<const float4*>(gamma);
    float4 a = xr[t], b = xr[t + 256];
    float4 ga = g4[t], gb = g4[t + 256];

    float ss = a.x*a.x + a.y*a.y + a.z*a.z + a.w*a.w
             + b.x*b.x + b.y*b.y + b.z*b.z + b.w*b.w;
    sh[t] = ss; __syncthreads();
    for (int o = 128; o > 0; o >>= 1) { if (t < o) sh[t] += sh[t + o]; __syncthreads(); }
    float rinv = 1.0f / sqrtf(sh[0] / (float)D_IN + 1e-6f);
    __syncthreads();

    float n0 = a.x*rinv*ga.x, n1 = a.y*rinv*ga.y, n2 = a.z*rinv*ga.z, n3 = a.w*rinv*ga.w;
    float n4 = b.x*rinv*gb.x, n5 = b.y*rinv*gb.y, n6 = b.z*rinv*gb.z, n7 = b.w*rinv*gb.w;

    float mx = fmaxf(fmaxf(fmaxf(fabsf(n0), fabsf(n1)), fmaxf(fabsf(n2), fabsf(n3))),
                     fmaxf(fmaxf(fabsf(n4), fabsf(n5)), fmaxf(fabsf(n6), fabsf(n7))));
    sh[t] = mx; __syncthreads();
    for (int o = 128; o > 0; o >>= 1) { if (t < o) sh[t] = fmaxf(sh[t], sh[t + o]); __syncthreads(); }
    float cmax = fmaxf(sh[0], 1e-5f);
    float scale = 127.0f / cmax;

    int q0 = (int)fminf(fmaxf(rintf(n0 * scale), -128.f), 127.f);
    int q1 = (int)fminf(fmaxf(rintf(n1 * scale), -128.f), 127.f);
    int q2 = (int)fminf(fmaxf(rintf(n2 * scale), -128.f), 127.f);
    int q3 = (int)fminf(fmaxf(rintf(n3 * scale), -128.f), 127.f);
    int q4 = (int)fminf(fmaxf(rintf(n4 * scale), -128.f), 127.f);
    int q5 = (int)fminf(fmaxf(rintf(n5 * scale), -128.f), 127.f);
    int q6 = (int)fminf(fmaxf(rintf(n6 * scale), -128.f), 127.f);
    int q7 = (int)fminf(fmaxf(rintf(n7 * scale), -128.f), 127.f);

    uint32_t* orow = reinterpret_cast<uint32_t*>(g_xa + (size_t)m * D_IN);
    orow[t]       = (uint32_t)(q0 & 0xFF) | ((uint32_t)(q1 & 0xFF) << 8)
                  | ((uint32_t)(q2 & 0xFF) << 16) | ((uint32_t)(q3 & 0xFF) << 24);
    orow[t + 256] = (uint32_t)(q4 & 0xFF) | ((uint32_t)(q5 & 0xFF) << 8)
                  | ((uint32_t)(q6 & 0xFF) << 16) | ((uint32_t)(q7 & 0xFF) << 24);

    if (t == 0) g_rowscale[m] = cmax * (1.0f / 127.0f);
}

// -------------------- int8 mma.sync GEMM --------------------
// out[m,n] = rowscale[m] * sum_k q[m,k] * t[n,k]   (exact s32 dot)
__global__ void __launch_bounds__(256, 2) k_gemm(float* __restrict__ out) {
    extern __shared__ char smem[];
    const uint32_t sbase = smem_u32(smem);
    const int tid = threadIdx.x;
    const int m0 = blockIdx.y * BM;
    const int n0 = blockIdx.x * BN;

    // --- cp.async slots: A 512 16B-chunks (2/thread), B 512 (2/thread)
    const int rA = tid >> 2;          // 0..63
    const int cc = tid & 3;           // 16B column
    const int8_t* pA0 = g_xa + ((size_t)(m0 + rA) * D_IN) + cc * 16;
    const int8_t* pA1 = pA0 + (size_t)64 * D_IN;
    const int8_t* pB0 = g_wt + ((size_t)(n0 + rA) * D_IN) + cc * 16;
    const int8_t* pB1 = pB0 + (size_t)64 * D_IN;
    const uint32_t dA0 = swz(rA, cc);
    const uint32_t dA1 = swz(rA + 64, cc);
    const uint32_t dB0 = (uint32_t)(BM * 64) + dA0;
    const uint32_t dB1 = (uint32_t)(BM * 64) + dA1;

    // --- warp tiling: 2(m) x 4(n) warps, warp tile 64x32
    const int w = tid >> 5, lane = tid & 31;
    const int wm = w & 1, wn = w >> 1;

    // ldmatrix addresses (relative to stage base)
    uint32_t aaddr[4][2], baddr[2][2];
#pragma unroll
    for (int mi = 0; mi < 4; mi++)
#pragma unroll
        for (int ks = 0; ks < 2; ks++)
            aaddr[mi][ks] = swz(wm * 64 + mi * 16 + (lane & 15), ks * 2 + (lane >> 4));
#pragma unroll
    for (int np = 0; np < 2; np++)
#pragma unroll
        for (int ks = 0; ks < 2; ks++)
            baddr[np][ks] = (uint32_t)(BM * 64)
                          + swz(wn * 32 + np * 16 + (lane & 15), ks * 2 + (lane >> 4));

    int acc[4][4][4];
#pragma unroll
    for (int mi = 0; mi < 4; mi++)
#pragma unroll
        for (int ni = 0; ni < 4; ni++)
#pragma unroll
            for (int r = 0; r < 4; r++) acc[mi][ni][r] = 0;

    // --- prologue: fill stages 0..2
#pragma unroll
    for (int s = 0; s < STAGES - 1; s++) {
        const uint32_t st = sbase + s * STAGE_BYTES;
        const int kb = s * BK;
        CP_ASYNC16(st + dA0, pA0 + kb);
        CP_ASYNC16(st + dA1, pA1 + kb);
        CP_ASYNC16(st + dB0, pB0 + kb);
        CP_ASYNC16(st + dB1, pB1 + kb);
        CP_COMMIT();
    }

    // --- main loop
    for (int kt = 0; kt < NKT; kt++) {
        CP_WAIT(STAGES - 2);
        __syncthreads();

        // issue next stage (overwrites stage consumed at kt-1; barrier above protects)
        if (kt + STAGES - 1 < NKT) {
            const uint32_t st = sbase + ((kt + STAGES - 1) & (STAGES - 1)) * STAGE_BYTES;
            const int kb = (kt + STAGES - 1) * BK;
            CP_ASYNC16(st + dA0, pA0 + kb);
            CP_ASYNC16(st + dA1, pA1 + kb);
            CP_ASYNC16(st + dB0, pB0 + kb);
            CP_ASYNC16(st + dB1, pB1 + kb);
        }
        CP_COMMIT();

        const uint32_t st = sbase + (kt & (STAGES - 1)) * STAGE_BYTES;
#pragma unroll
        for (int ks = 0; ks < 2; ks++) {
            uint32_t RA[4][4], RB[2][4];
#pragma unroll
            for (int mi = 0; mi < 4; mi++) LDSM_X4(RA[mi], st + aaddr[mi][ks]);
#pragma unroll
            for (int np = 0; np < 2; np++) LDSM_X4(RB[np], st + baddr[np][ks]);
#pragma unroll
            for (int mi = 0; mi < 4; mi++)
#pragma unroll
                for (int ni = 0; ni < 4; ni++) {
                    const int np = ni >> 1, hi = ni & 1;
                    MMA_S8(acc[mi][ni], RA[mi], RB[np][hi], RB[np][hi + 2]);
                }
        }
    }

    // --- epilogue: scale by rowscale[m], float2 stores
#pragma unroll
    for (int mi = 0; mi < 4; mi++) {
        const int r0 = m0 + wm * 64 + mi * 16 + (lane >> 2);
        const float rs0 = g_rowscale[r0];
        const float rs1 = g_rowscale[r0 + 8];
        float* o0 = out + (size_t)r0 * D_OUT + n0 + wn * 32 + (lane & 3) * 2;
        float* o1 = o0 + (size_t)8 * D_OUT;
#pragma unroll
        for (int ni = 0; ni < 4; ni++) {
            float2 v0, v1;
            v0.x = (float)acc[mi][ni][0] * rs0;
            v0.y = (float)acc[mi][ni][1] * rs0;
            v1.x = (float)acc[mi][ni][2] * rs1;
            v1.y = (float)acc[mi][ni][3] * rs1;
            *reinterpret_cast<float2*>(o0 + ni * 8) = v0;
            *reinterpret_cast<float2*>(o1 + ni * 8) = v1;
        }
    }
}

// -------------------- launch --------------------
extern "C" void kernel_launch(void* const* d_in, const int* in_sizes, int n_in,
                              void* d_out, int out_size) {
    const float* x     = (const float*)d_in[0];
    const float* wt    = (const float*)d_in[1];
    const float* gamma = (const float*)d_in[2];
    float* out = (float*)d_out;

    k_wsum1<<<4096, 256>>>(wt);
    k_wsum2<<<1, 256>>>();
    k_tern<<<(D_OUT * D_IN) / (4 * 256), 256>>>(wt);
    k_actq<<<M_TOT, 256>>>(x, gamma);

    cudaFuncSetAttribute(k_gemm, cudaFuncAttributeMaxDynamicSharedMemorySize, SMEM_BYTES);
    dim3 grid(D_OUT / BN, M_TOT / BM);
    k_gemm<<<grid, 256, SMEM_BYTES>>>(out);
}